// round 12
// baseline (speedup 1.0000x reference)
#include <cuda_runtime.h>
#include <math.h>

#define BN    737280      // total elements (8 * 92160)
#define BNH   368640      // BN / 2 (k1 ILP split)
#define NPIX  92160       // elements per (b,t) slice
#define NTRK  512
#define NSEG  4096        // 8 * 512
#define NCH   66
#define WCH   68          // wsum accumulator row stride (16B-aligned)
#define WSR   72          // srow stride (288B = 32B-multiple, sector-aligned)
#define WST   68          // smem stage row stride (16B-aligned per element)
#define REPL  4           // accumulator replicas (contention spreading)
#define THR   2.0f
#define DKS   0.05f

// ---------------- scratch (device globals; no allocation) ----------------
struct Scratch {
    int    cnt[REPL * NSEG];
    float4 p1[REPL * NSEG];              // {z1, wx, wy, wz}
    float  wsum[REPL * NSEG * WCH];      // [0..65]=w*ch, [66]=z2
};
__device__ __align__(16) Scratch        g_s;
__device__ unsigned long long           g_repkey[REPL * NSEG];  // (~fok(k0))<<32 | idx
__device__ __align__(32) float          g_srow[NSEG * WSR];     // finalized segment row
__device__ int                          g_rep[NSEG];
__device__ unsigned char                g_flags[BN];

// ordered-uint mapping for floats (bijective, order-preserving)
__device__ __forceinline__ unsigned fok(float f) {
    unsigned b = __float_as_uint(f);
    return (b & 0x80000000u) ? ~b : (b | 0x80000000u);
}
__device__ __forceinline__ float kof(unsigned u) {
    unsigned b = (u & 0x80000000u) ? (u & 0x7FFFFFFFu) : ~u;
    return __uint_as_float(b);
}
__device__ __forceinline__ int seg_of(int i, int g) {
    return (i / NPIX) * NTRK + g;
}
__device__ __forceinline__ void red_add_v4(float* p, float a, float b, float c, float d) {
    asm volatile("red.global.add.v4.f32 [%0], {%1, %2, %3, %4};"
                 :: "l"(p), "f"(a), "f"(b), "f"(c), "f"(d) : "memory");
}

// load all 66 channels for element i into buf (k2 only)
__device__ __forceinline__ void load_row(
    int i, float* buf,
    const float* __restrict__ cen, const float* __restrict__ off,
    const float* __restrict__ opa, const float* __restrict__ sca,
    const float* __restrict__ rot, const float* __restrict__ fdc,
    const float* __restrict__ kp,  const float* __restrict__ ins,
    const float* __restrict__ mot) {
    #pragma unroll
    for (int c = 0; c < 3; c++) buf[c]      = cen[3 * i + c];
    #pragma unroll
    for (int c = 0; c < 3; c++) buf[3 + c]  = off[3 * i + c];
    buf[6] = opa[i];
    #pragma unroll
    for (int c = 0; c < 3; c++) buf[7 + c]  = sca[3 * i + c];
    {
        float4 r4 = reinterpret_cast<const float4*>(rot)[i];
        buf[10] = r4.x; buf[11] = r4.y; buf[12] = r4.z; buf[13] = r4.w;
    }
    #pragma unroll
    for (int c = 0; c < 3; c++) buf[14 + c] = fdc[3 * i + c];
    buf[17] = kp[i];
    const float4* ip = reinterpret_cast<const float4*>(ins) + (size_t)i * 8;
    #pragma unroll
    for (int q = 0; q < 8; q++) {
        float4 v = ip[q];
        buf[18 + 4 * q + 0] = v.x; buf[18 + 4 * q + 1] = v.y;
        buf[18 + 4 * q + 2] = v.z; buf[18 + 4 * q + 3] = v.w;
    }
    const float4* mp = reinterpret_cast<const float4*>(mot) + (size_t)i * 4;
    #pragma unroll
    for (int q = 0; q < 4; q++) {
        float4 v = mp[q];
        buf[50 + 4 * q + 0] = v.x; buf[50 + 4 * q + 1] = v.y;
        buf[50 + 4 * q + 2] = v.z; buf[50 + 4 * q + 3] = v.w;
    }
}

// ---------------- kernels ----------------
// count + phase-1 softmax sums into per-replica accumulators (2 elems/thread)
__global__ void __launch_bounds__(256)
k1(const float* __restrict__ cen, const float* __restrict__ kp,
   const int* __restrict__ gid) {
    int t = blockIdx.x * blockDim.x + threadIdx.x;
    int rbase = (blockIdx.x & (REPL - 1)) * NSEG;
    #pragma unroll
    for (int h = 0; h < 2; h++) {
        int i = t + h * BNH;
        int g = gid[i];
        if (g >= 0) {
            int s = seg_of(i, g) + rbase;
            atomicAdd(&g_s.cnt[s], 1);
            float e = __expf(kp[i]);
            red_add_v4(&g_s.p1[s].x, e,
                       e * cen[3 * i + 0], e * cen[3 * i + 1], e * cen[3 * i + 2]);
        }
    }
}

// activity + weighted accumulation (per-replica) + representative key.
// Phase-1 replicas are summed inline (L1/L2-resident table).
__global__ void __launch_bounds__(256)
k2(const float* __restrict__ cen, const float* __restrict__ off,
   const float* __restrict__ opa, const float* __restrict__ sca,
   const float* __restrict__ rot, const float* __restrict__ fdc,
   const float* __restrict__ kp,  const float* __restrict__ ins,
   const float* __restrict__ mot, const int* __restrict__ gid) {
    int i = blockIdx.x * blockDim.x + threadIdx.x;
    if (i >= BN) return;
    int g = gid[i];
    int s = 0;
    unsigned char f = 0;
    float k0 = 0.0f;
    if (g >= 0) {
        s = seg_of(i, g);
        int cnt = 0;
        float z1 = 0.f, wx = 0.f, wy = 0.f, wz = 0.f;
        #pragma unroll
        for (int r = 0; r < REPL; r++) {
            cnt += __ldg(&g_s.cnt[r * NSEG + s]);
            float4 p = __ldg(&g_s.p1[r * NSEG + s]);
            z1 += p.x; wx += p.y; wy += p.z; wz += p.w;
        }
        if (cnt >= 2) {
            float zinv = 1.0f / fmaxf(z1, 1e-20f);
            float dx = cen[3 * i + 0] - wx * zinv;
            float dy = cen[3 * i + 1] - wy * zinv;
            float dz = cen[3 * i + 2] - wz * zinv;
            if (sqrtf(dx * dx + dy * dy + dz * dz) <= THR) {
                f = 1;
                k0 = kp[i];
            }
        }
    }
    g_flags[i] = f;
    if (!f) return;

    float buf[NCH];
    load_row(i, buf, cen, off, opa, sca, rot, fdc, kp, ins, mot);
    float e = __expf(k0);
    int sr = s + (blockIdx.x & (REPL - 1)) * NSEG;
    float* ws = &g_s.wsum[(size_t)sr * WCH];
    #pragma unroll
    for (int q = 0; q < 16; q++)
        red_add_v4(ws + 4 * q,
                   e * buf[4 * q + 0], e * buf[4 * q + 1],
                   e * buf[4 * q + 2], e * buf[4 * q + 3]);
    red_add_v4(ws + 64, e * buf[64], e * buf[65], e, 0.0f);

    unsigned long long key =
        ((unsigned long long)(~fok(k0)) << 32) | (unsigned)i;
    atomicMin(&g_repkey[sr], key);
}

// warp-per-segment finalize: collapse replicas, means, rotation norm, mkeep, rep
__global__ void __launch_bounds__(256)
k_seg() {
    const unsigned FULL = 0xFFFFFFFFu;
    int warp = (blockIdx.x * blockDim.x + threadIdx.x) >> 5;
    int lane = threadIdx.x & 31;
    if (warp >= NSEG) return;
    int s = warp;

    float a0 = 0.f, a1 = 0.f, a2 = 0.f;
    #pragma unroll
    for (int r = 0; r < REPL; r++) {
        const float* ws = &g_s.wsum[(size_t)(r * NSEG + s) * WCH];
        a0 += ws[lane];
        a1 += ws[lane + 32];
        if (lane < 4) a2 += ws[lane + 64];
    }
    float z2   = __shfl_sync(FULL, a2, 2);     // z2 = channel 66
    float zinv = 1.0f / fmaxf(z2, 1e-20f);
    a0 *= zinv; a1 *= zinv; a2 *= zinv;

    float r10 = __shfl_sync(FULL, a0, 10);
    float r11 = __shfl_sync(FULL, a0, 11);
    float r12 = __shfl_sync(FULL, a0, 12);
    float r13 = __shfl_sync(FULL, a0, 13);
    float nr  = sqrtf(r10 * r10 + r11 * r11 + r12 * r12 + r13 * r13);
    float ri  = 1.0f / fmaxf(nr, 1e-12f);
    if (lane >= 10 && lane <= 13) a0 *= ri;

    unsigned long long key = 0xFFFFFFFFFFFFFFFFull;
    if (lane == 0) {
        #pragma unroll
        for (int r = 0; r < REPL; r++) {
            unsigned long long k = g_repkey[r * NSEG + s];
            if (k < key) key = k;
        }
        g_rep[s] = (int)(unsigned)(key & 0xFFFFFFFFull);
    }
    key = __shfl_sync(FULL, key, 0);
    float m2 = kof(~(unsigned)(key >> 32));
    if (lane == 17) a0 = m2;   // mkeep = segment max keep over active

    float* r = &g_srow[(size_t)s * WSR];
    r[lane]      = a0;
    r[lane + 32] = a1;
    if (lane < 2) r[lane + 64] = a2;   // channels 64, 65
}

// output kernel: 512 threads / 128 elements per block (quad per element).
// Active: 4 lanes cooperatively gather the srow row (64B-contiguous LDG.128
// per quad -> 2 sectors/element/instr). Inactive: quad lanes split the raw
// source arrays. Stage padded to 68 floats; readout repacks to 66 coalesced.
__global__ void __launch_bounds__(512)
k3(const float* __restrict__ cen, const float* __restrict__ off,
   const float* __restrict__ opa, const float* __restrict__ sca,
   const float* __restrict__ rot, const float* __restrict__ fdc,
   const float* __restrict__ kp,  const float* __restrict__ ins,
   const float* __restrict__ mot, const int* __restrict__ gid,
   float* __restrict__ out) {
    __shared__ float stage[128 * WST];   // 34,816 B
    int tid = threadIdx.x;
    int e   = tid >> 2;                  // element slot 0..127
    int j   = tid & 3;                   // quad lane
    int i   = blockIdx.x * 128 + e;

    float* st = &stage[e * WST];
    if (g_flags[i]) {
        int s = seg_of(i, gid[i]);
        float sfac = (i == g_rep[s]) ? 1.0f : DKS;
        const float4* r4 = reinterpret_cast<const float4*>(&g_srow[(size_t)s * WSR]);
        #pragma unroll
        for (int it = 0; it < 5; it++) {
            int q = j + 4 * it;
            if (q < 17) {
                float4 v = __ldg(r4 + q);
                if (q == 1) v.z *= sfac;   // channel 6 (opacity)
                if (q == 4) v.y *= sfac;   // channel 17 (keep)
                *reinterpret_cast<float4*>(st + 4 * q) = v;
            }
        }
    } else {
        if (j == 0) {
            st[0] = cen[3 * i]; st[1] = cen[3 * i + 1]; st[2] = cen[3 * i + 2];
            st[3] = off[3 * i]; st[4] = off[3 * i + 1]; st[5] = off[3 * i + 2];
            st[6] = opa[i];
            st[7] = sca[3 * i]; st[8] = sca[3 * i + 1]; st[9] = sca[3 * i + 2];
        } else if (j == 1) {
            float4 rv = reinterpret_cast<const float4*>(rot)[i];
            st[10] = rv.x; st[11] = rv.y; st[12] = rv.z; st[13] = rv.w;
            st[14] = fdc[3 * i]; st[15] = fdc[3 * i + 1]; st[16] = fdc[3 * i + 2];
            st[17] = kp[i];
        } else if (j == 2) {
            const float4* ip = reinterpret_cast<const float4*>(ins) + (size_t)i * 8;
            #pragma unroll
            for (int q = 0; q < 8; q++) {
                float4 v = ip[q];
                st[18 + 4 * q + 0] = v.x; st[18 + 4 * q + 1] = v.y;
                st[18 + 4 * q + 2] = v.z; st[18 + 4 * q + 3] = v.w;
            }
        } else {
            const float4* mp = reinterpret_cast<const float4*>(mot) + (size_t)i * 4;
            #pragma unroll
            for (int q = 0; q < 4; q++) {
                float4 v = mp[q];
                st[50 + 4 * q + 0] = v.x; st[50 + 4 * q + 1] = v.y;
                st[50 + 4 * q + 2] = v.z; st[50 + 4 * q + 3] = v.w;
            }
        }
    }
    __syncthreads();

    // repack padded-68 stage -> packed-66 rows, fully coalesced STG.128
    float4* dst = reinterpret_cast<float4*>(out + (size_t)blockIdx.x * 128 * NCH);
    for (int f4 = tid; f4 < (128 * NCH) / 4; f4 += 512) {
        int f   = 4 * f4;
        int row = f / NCH;
        int c   = f - row * NCH;      // even, 0..64
        const float* sp = &stage[row * WST + c];
        float4 v;
        if (c <= 62) {
            v.x = sp[0]; v.y = sp[1]; v.z = sp[2]; v.w = sp[3];
        } else {                      // c == 64: spans into next row
            const float* sp2 = &stage[(row + 1) * WST];
            v.x = sp[0]; v.y = sp[1]; v.z = sp2[0]; v.w = sp2[1];
        }
        dst[f4] = v;
    }
}

// ---------------- launcher ----------------
extern "C" void kernel_launch(void* const* d_in, const int* in_sizes, int n_in,
                              void* d_out, int out_size) {
    const float* cen = (const float*)d_in[0];
    const float* off = (const float*)d_in[1];
    const float* opa = (const float*)d_in[2];
    const float* sca = (const float*)d_in[3];
    const float* rot = (const float*)d_in[4];
    const float* fdc = (const float*)d_in[5];
    const float* kp  = (const float*)d_in[6];
    const float* ins = (const float*)d_in[7];
    const float* mot = (const float*)d_in[8];
    const int*   gid = (const int*)d_in[9];
    float* out = (float*)d_out;

    void *p_s, *p_key;
    cudaGetSymbolAddress(&p_s,   g_s);
    cudaGetSymbolAddress(&p_key, g_repkey);
    cudaMemsetAsync(p_s,   0,    sizeof(Scratch));
    cudaMemsetAsync(p_key, 0xFF, (size_t)REPL * NSEG * sizeof(unsigned long long));

    const int TB = 256;
    k1   <<<BNH / TB, TB>>>(cen, kp, gid);
    k2   <<<BN / TB, TB>>>(cen, off, opa, sca, rot, fdc, kp, ins, mot, gid);
    k_seg<<<(NSEG * 32) / TB, TB>>>();
    k3   <<<BN / 128, 512>>>(cen, off, opa, sca, rot, fdc, kp, ins, mot, gid, out);
}